// round 2
// baseline (speedup 1.0000x reference)
#include <cuda_runtime.h>
#include <cuda_bf16.h>

// Problem constants (fixed shapes)
#define B_BATCH 64
#define C_CH    862
#define S_LEN   720
#define P_OUT   336
#define G_CL    8

#define BM 64   // batch tile (all batches)
#define BN 64   // output-P tile
#define BK 16   // K tile
#define TM 4
#define TN 4

// Decoded cluster ids (handles int32 vs int64 source dtype)
__device__ int g_clusters[C_CH];

// clusters tensor may be int32 (JAX default, x64 disabled) or int64 (x64 on).
// Detect by sniffing the first 32 words: if all odd words are zero, the buffer
// is little-endian int64 (high words of values 0..7 are always 0). True int32
// data (random 0..7) has all-zero odd words with prob (1/8)^16 ~ 0.
__global__ void decode_clusters_kernel(const int* __restrict__ cl) {
    __shared__ int is64_s;
    if (threadIdx.x == 0) {
        int odd_zero = 1;
        #pragma unroll
        for (int i = 1; i < 32; i += 2) odd_zero &= (cl[i] == 0);
        is64_s = odd_zero;
    }
    __syncthreads();
    const int is64 = is64_s;
    for (int c = threadIdx.x; c < C_CH; c += blockDim.x) {
        g_clusters[c] = is64 ? cl[2 * c] : cl[c];
    }
}

__global__ __launch_bounds__(256, 4)
void clustered_linear_kernel(const float* __restrict__ x,
                             const float* __restrict__ W,
                             const float* __restrict__ bias,
                             float* __restrict__ out) {
    const int c  = blockIdx.y;
    const int p0 = blockIdx.x * BN;
    const int g  = g_clusters[c];

    const float* __restrict__ Wg = W + (size_t)g * P_OUT * S_LEN;
    const float* __restrict__ xc = x + (size_t)c * S_LEN;

    __shared__ float As[BK][BM + 4];  // As[k][b], row stride 68 floats = 272B (16B-aligned)
    __shared__ float Ws[BK][BN + 4];  // Ws[k][p]

    const int tid = threadIdx.x;
    const int tx = tid & 15;   // P micro-tile index
    const int ty = tid >> 4;   // batch micro-tile index

    // Load indices: 256 threads load a 64x16 float tile as float4s.
    const int lr = tid >> 2;         // 0..63 (row)
    const int lc = (tid & 3) * 4;    // 0,4,8,12 (k offset)

    float acc[TM][TN];
    #pragma unroll
    for (int i = 0; i < TM; i++)
        #pragma unroll
        for (int j = 0; j < TN; j++) acc[i][j] = 0.0f;

    const size_t x_row_stride = (size_t)C_CH * S_LEN;

    for (int k0 = 0; k0 < S_LEN; k0 += BK) {
        // x tile: batch=lr, s = k0+lc .. +3  (each row contiguous, 16B aligned)
        float4 xa = *reinterpret_cast<const float4*>(xc + (size_t)lr * x_row_stride + k0 + lc);
        As[lc + 0][lr] = xa.x;
        As[lc + 1][lr] = xa.y;
        As[lc + 2][lr] = xa.z;
        As[lc + 3][lr] = xa.w;

        // W tile: p = p0+lr, s = k0+lc .. +3, predicated on p < P
        float4 wa = make_float4(0.f, 0.f, 0.f, 0.f);
        if (p0 + lr < P_OUT)
            wa = *reinterpret_cast<const float4*>(Wg + (size_t)(p0 + lr) * S_LEN + k0 + lc);
        Ws[lc + 0][lr] = wa.x;
        Ws[lc + 1][lr] = wa.y;
        Ws[lc + 2][lr] = wa.z;
        Ws[lc + 3][lr] = wa.w;

        __syncthreads();

        #pragma unroll
        for (int k = 0; k < BK; k++) {
            const float4 a = *reinterpret_cast<const float4*>(&As[k][ty * TM]);
            const float4 w = *reinterpret_cast<const float4*>(&Ws[k][tx * TN]);
            acc[0][0] += a.x * w.x; acc[0][1] += a.x * w.y; acc[0][2] += a.x * w.z; acc[0][3] += a.x * w.w;
            acc[1][0] += a.y * w.x; acc[1][1] += a.y * w.y; acc[1][2] += a.y * w.z; acc[1][3] += a.y * w.w;
            acc[2][0] += a.z * w.x; acc[2][1] += a.z * w.y; acc[2][2] += a.z * w.z; acc[2][3] += a.z * w.w;
            acc[3][0] += a.w * w.x; acc[3][1] += a.w * w.y; acc[3][2] += a.w * w.z; acc[3][3] += a.w * w.w;
        }

        __syncthreads();
    }

    // Epilogue: add bias, store float4 (P=336 is a multiple of 4; tiles of 4 aligned)
    const float* __restrict__ bg = bias + g * P_OUT;
    const int p = p0 + tx * TN;
    if (p + 3 < P_OUT) {
        const float4 bv = *reinterpret_cast<const float4*>(bg + p);
        #pragma unroll
        for (int i = 0; i < TM; i++) {
            const int bb = ty * TM + i;
            float4 o;
            o.x = acc[i][0] + bv.x;
            o.y = acc[i][1] + bv.y;
            o.z = acc[i][2] + bv.z;
            o.w = acc[i][3] + bv.w;
            *reinterpret_cast<float4*>(out + ((size_t)bb * C_CH + c) * P_OUT + p) = o;
        }
    }
}

extern "C" void kernel_launch(void* const* d_in, const int* in_sizes, int n_in,
                              void* d_out, int out_size) {
    const float* x        = (const float*)d_in[0];
    const int*   clusters = (const int*)d_in[1];   // int32 or int64; decoded on device
    const float* W        = (const float*)d_in[2];
    const float* bias     = (const float*)d_in[3];
    float*       out      = (float*)d_out;

    decode_clusters_kernel<<<1, 896>>>(clusters);

    dim3 grid((P_OUT + BN - 1) / BN, C_CH);  // (6, 862)
    clustered_linear_kernel<<<grid, 256>>>(x, W, bias, out);
}

// round 5
// speedup vs baseline: 2.9467x; 2.9467x over previous
#include <cuda_runtime.h>
#include <cuda_bf16.h>
#include <cstdint>

#define B_BATCH 64
#define C_CH    862
#define S_LEN   720
#define P_OUT   336
#define G_CL    8
#define KC      32
#define NCHK    23          // ceil(720/32); chunk 22 is half zero-padded
#define K_PAD   736
#define MAX_TASKS 435
#define THREADS 512

// ---------------- device scratch ----------------
__device__ int g_task_c0[MAX_TASKS];
__device__ int g_task_c1[MAX_TASKS];
__device__ int g_task_g[MAX_TASKS];
__device__ int g_cl[C_CH];
__device__ int g_order[C_CH];
__device__ int g_cnt[G_CL];
__device__ int g_off[G_CL];
__device__ int g_pairoff[G_CL + 1];
__device__ int g_cursor[G_CL];

// Pre-converted W (bf16 hi/lo), K padded to 736 with zeros. ~7.9 MB statics.
__device__ __nv_bfloat16 g_Whi[G_CL * P_OUT * K_PAD];
__device__ __nv_bfloat16 g_Wlo[G_CL * P_OUT * K_PAD];

// ---------------- helpers ----------------
__device__ __forceinline__ uint32_t smem_u32(const void* p) {
    uint32_t a;
    asm("{ .reg .u64 t; cvta.to.shared.u64 t, %1; cvt.u32.u64 %0, t; }" : "=r"(a) : "l"(p));
    return a;
}
__device__ __forceinline__ uint32_t swz64(uint32_t o) { return o ^ ((o >> 3) & 0x30); }

__device__ __forceinline__ void ldsm4(uint32_t* r, uint32_t addr) {
    asm volatile("ldmatrix.sync.aligned.m8n8.x4.shared.b16 {%0,%1,%2,%3}, [%4];"
                 : "=r"(r[0]), "=r"(r[1]), "=r"(r[2]), "=r"(r[3]) : "r"(addr));
}
__device__ __forceinline__ void ldsm2(uint32_t* r, uint32_t addr) {
    asm volatile("ldmatrix.sync.aligned.m8n8.x2.shared.b16 {%0,%1}, [%2];"
                 : "=r"(r[0]), "=r"(r[1]) : "r"(addr));
}
__device__ __forceinline__ void mma16816(float* c, const uint32_t* a, uint32_t b0, uint32_t b1) {
    asm volatile(
        "mma.sync.aligned.m16n8k16.row.col.f32.bf16.bf16.f32 "
        "{%0,%1,%2,%3}, {%4,%5,%6,%7}, {%8,%9}, {%0,%1,%2,%3};"
        : "+f"(c[0]), "+f"(c[1]), "+f"(c[2]), "+f"(c[3])
        : "r"(a[0]), "r"(a[1]), "r"(a[2]), "r"(a[3]), "r"(b0), "r"(b1));
}
__device__ __forceinline__ void cpasync16(uint32_t dst, const void* src) {
    asm volatile("cp.async.cg.shared.global [%0], [%1], 16;" :: "r"(dst), "l"(src) : "memory");
}
__device__ __forceinline__ void cp_commit() { asm volatile("cp.async.commit_group;" ::: "memory"); }
__device__ __forceinline__ void cp_wait0()  { asm volatile("cp.async.wait_group 0;" ::: "memory"); }

__device__ __forceinline__ uint32_t pack2(__nv_bfloat16 a, __nv_bfloat16 b) {
    uint16_t ua = *reinterpret_cast<uint16_t*>(&a);
    uint16_t ub = *reinterpret_cast<uint16_t*>(&b);
    return (uint32_t)ua | ((uint32_t)ub << 16);
}
// Store 4 floats as bf16 hi into hi tile and residual lo into lo tile (8B each, swizzled).
__device__ __forceinline__ void store_hi_lo(char* hi_t, char* lo_t, uint32_t boff, float4 v) {
    __nv_bfloat16 h0 = __float2bfloat16(v.x), h1 = __float2bfloat16(v.y),
                  h2 = __float2bfloat16(v.z), h3 = __float2bfloat16(v.w);
    float l0 = v.x - __bfloat162float(h0), l1 = v.y - __bfloat162float(h1),
          l2 = v.z - __bfloat162float(h2), l3 = v.w - __bfloat162float(h3);
    uint2 hp, lp;
    hp.x = pack2(h0, h1); hp.y = pack2(h2, h3);
    lp.x = pack2(__float2bfloat16(l0), __float2bfloat16(l1));
    lp.y = pack2(__float2bfloat16(l2), __float2bfloat16(l3));
    uint32_t s = swz64(boff);
    *reinterpret_cast<uint2*>(hi_t + s) = hp;
    *reinterpret_cast<uint2*>(lo_t + s) = lp;
}

// ---------------- SMEM layout ----------------
#define SM_BIAS   0          // 336 * 4 = 1344
#define SM_BUF0   2048
#define OFF_AHI   0          // 128 rows * 64B = 8192
#define OFF_ALO   8192
#define OFF_BHI   16384      // 336 rows * 64B = 21504
#define OFF_BLO   37888
#define BUF_BYTES 59392
#define SMEM_TOTAL (SM_BUF0 + 2 * BUF_BYTES)  // 120832

// ---------------- prep: decode clusters, group, pair ----------------
__global__ void prep_kernel(const int* __restrict__ cl) {
    __shared__ int is64_s;
    const int tid = threadIdx.x;
    if (tid == 0) {
        int odd_zero = 1;
        #pragma unroll
        for (int i = 1; i < 32; i += 2) odd_zero &= (cl[i] == 0);
        is64_s = odd_zero;
    }
    if (tid < G_CL) { g_cnt[tid] = 0; g_cursor[tid] = 0; }
    __syncthreads();
    const int is64 = is64_s;
    for (int c = tid; c < C_CH; c += blockDim.x) {
        int g = is64 ? cl[2 * c] : cl[c];
        g_cl[c] = g;
        atomicAdd(&g_cnt[g], 1);
    }
    __syncthreads();
    if (tid == 0) {
        int o = 0, po = 0;
        for (int g = 0; g < G_CL; g++) {
            g_off[g] = o; g_pairoff[g] = po;
            o += g_cnt[g]; po += (g_cnt[g] + 1) >> 1;
        }
        g_pairoff[G_CL] = po;
    }
    __syncthreads();
    for (int c = tid; c < C_CH; c += blockDim.x) {
        int g = g_cl[c];
        int pos = g_off[g] + atomicAdd(&g_cursor[g], 1);
        g_order[pos] = c;
    }
    __syncthreads();
    const int total = g_pairoff[G_CL];
    for (int t = tid; t < MAX_TASKS; t += blockDim.x) {
        int c0 = -1, c1 = -1, gg = 0;
        if (t < total) {
            int g = 0;
            while (t >= g_pairoff[g + 1]) g++;
            int p = t - g_pairoff[g];
            c0 = g_order[g_off[g] + 2 * p];
            c1 = (2 * p + 1 < g_cnt[g]) ? g_order[g_off[g] + 2 * p + 1] : -1;
            gg = g;
        }
        g_task_c0[t] = c0; g_task_c1[t] = c1; g_task_g[t] = gg;
    }
}

// ---------------- W fp32 -> bf16 hi/lo (once, zero-padded K) ----------------
__global__ void convw_kernel(const float* __restrict__ W) {
    int idx = blockIdx.x * 256 + threadIdx.x;
    if (idx >= G_CL * P_OUT * K_PAD) return;
    int k = idx % K_PAD;
    int row = idx / K_PAD;
    float v = (k < S_LEN) ? W[(size_t)row * S_LEN + k] : 0.0f;
    __nv_bfloat16 h = __float2bfloat16(v);
    g_Whi[idx] = h;
    g_Wlo[idx] = __float2bfloat16(v - __bfloat162float(h));
}

// ---------------- main GEMM kernel (mma.sync bf16x3) ----------------
__global__ __launch_bounds__(THREADS, 1)
void mm_kernel(const float* __restrict__ x,
               const float* __restrict__ bias,
               float* __restrict__ out) {
    const int task = blockIdx.x;
    const int c0 = g_task_c0[task];
    if (c0 < 0) return;
    const int c1 = g_task_c1[task];
    const int g  = g_task_g[task];

    extern __shared__ char smem[];
    const uint32_t sbase = smem_u32(smem);
    const int tid  = threadIdx.x;
    const int lane = tid & 31;
    const int wid  = tid >> 5;
    const int warp_m = wid & 7;      // 8 m-slices of 16 rows
    const int warp_n = wid >> 3;     // 2 n-slices of 168

    for (int j = tid; j < P_OUT; j += THREADS)
        *reinterpret_cast<float*>(smem + SM_BIAS + 4 * j) = bias[g * P_OUT + j];

    // Per-lane swizzled base offsets (within region, chunk-invariant).
    const uint32_t a_swz  = swz64((uint32_t)((warp_m * 16 + (lane & 15)) * 64 + ((lane >> 4) & 1) * 16));
    const uint32_t b_swz  = swz64((uint32_t)((((lane >> 4) & 1) * 8 + (lane & 7)) * 64 + ((lane >> 3) & 1) * 16));
    const uint32_t b2_swz = swz64((uint32_t)((lane & 7) * 64 + ((lane >> 3) & 1) * 16));
    const uint32_t bn_off = (uint32_t)(warp_n * 168 * 64);  // n-slice byte offset (multiple of 8 rows)

    const __nv_bfloat16* whi = g_Whi + (size_t)g * P_OUT * K_PAD;
    const __nv_bfloat16* wlo = g_Wlo + (size_t)g * P_OUT * K_PAD;

    float acc[21][4];
    #pragma unroll
    for (int i = 0; i < 21; i++)
        #pragma unroll
        for (int j = 0; j < 4; j++) acc[i][j] = 0.0f;

    // ---- chunk loaders ----
    auto loadA = [&](int chunk, int buf) {
        char* bptr = smem + SM_BUF0 + buf * BUF_BYTES;
        const int k0 = chunk * KC;
        #pragma unroll
        for (int it = 0; it < 2; it++) {
            int idx = tid + it * THREADS;       // 0..1023
            int row = idx >> 3;                 // 0..127
            int col4 = (idx & 7) << 2;          // 0..28
            int ch = (row < 64) ? c0 : c1;
            float4 v = make_float4(0.f, 0.f, 0.f, 0.f);
            if (ch >= 0 && (k0 + col4 + 3) < S_LEN)
                v = *reinterpret_cast<const float4*>(
                        x + ((size_t)(row & 63) * C_CH + ch) * S_LEN + k0 + col4);
            store_hi_lo(bptr + OFF_AHI, bptr + OFF_ALO, (uint32_t)(row * 64 + col4 * 2), v);
        }
    };
    auto issueB = [&](int chunk, int buf) {
        const uint32_t bufb = sbase + SM_BUF0 + buf * BUF_BYTES;
        const int k0 = chunk * KC;
        for (int e = tid; e < 2688; e += THREADS) {
            int hi = (e < 1344);
            int ee = hi ? e : e - 1344;
            int row = ee >> 2;
            int unit = ee & 3;
            uint32_t dst = bufb + (hi ? OFF_BHI : OFF_BLO) + swz64((uint32_t)(row * 64 + unit * 16));
            const __nv_bfloat16* src = (hi ? whi : wlo) + (size_t)row * K_PAD + k0 + unit * 8;
            cpasync16(dst, src);
        }
        cp_commit();
    };

    // ---- pipeline ----
    loadA(0, 0);
    issueB(0, 0);

    for (int i = 0; i < NCHK; i++) {
        const int buf = i & 1;
        cp_wait0();
        __syncthreads();
        if (i + 1 < NCHK) { loadA(i + 1, buf ^ 1); issueB(i + 1, buf ^ 1); }

        const uint32_t bufb = sbase + SM_BUF0 + buf * BUF_BYTES;
        #pragma unroll
        for (int k16 = 0; k16 < 2; k16++) {
            const uint32_t ko = (uint32_t)(k16 << 5);
            uint32_t ah[4], al[4];
            ldsm4(ah, bufb + OFF_AHI + (a_swz ^ ko));
            ldsm4(al, bufb + OFF_ALO + (a_swz ^ ko));
            const uint32_t bhib = bufb + OFF_BHI + bn_off;
            const uint32_t blob = bufb + OFF_BLO + bn_off;
            #pragma unroll
            for (int p = 0; p < 10; p++) {
                uint32_t bh[4], bl[4];
                ldsm4(bh, bhib + p * 1024 + (b_swz ^ ko));
                ldsm4(bl, blob + p * 1024 + (b_swz ^ ko));
                mma16816(acc[2 * p],     ah, bh[0], bh[1]);
                mma16816(acc[2 * p],     al, bh[0], bh[1]);
                mma16816(acc[2 * p],     ah, bl[0], bl[1]);
                mma16816(acc[2 * p + 1], ah, bh[2], bh[3]);
                mma16816(acc[2 * p + 1], al, bh[2], bh[3]);
                mma16816(acc[2 * p + 1], ah, bl[2], bl[3]);
            }
            uint32_t bh2[2], bl2[2];
            ldsm2(bh2, bhib + 10240 + (b2_swz ^ ko));
            ldsm2(bl2, blob + 10240 + (b2_swz ^ ko));
            mma16816(acc[20], ah, bh2[0], bh2[1]);
            mma16816(acc[20], al, bh2[0], bh2[1]);
            mma16816(acc[20], ah, bl2[0], bl2[1]);
        }
    }

    // ---- epilogue ----
    const int chan = (warp_m < 4) ? c0 : c1;
    if (chan < 0) return;
    const int r0 = warp_m * 16 + (lane >> 2);        // 0..127
    const int ncol = warp_n * 168 + (lane & 3) * 2;
    float* o0 = out + ((size_t)(r0 & 63) * C_CH + chan) * P_OUT + ncol;
    float* o1 = out + ((size_t)((r0 + 8) & 63) * C_CH + chan) * P_OUT + ncol;
    const char* bsm = smem + SM_BIAS + 4 * ncol;
    #pragma unroll
    for (int nf = 0; nf < 21; nf++) {
        float2 bv = *reinterpret_cast<const float2*>(bsm + nf * 32);
        float2 v0 = make_float2(acc[nf][0] + bv.x, acc[nf][1] + bv.y);
        float2 v1 = make_float2(acc[nf][2] + bv.x, acc[nf][3] + bv.y);
        *reinterpret_cast<float2*>(o0 + nf * 8) = v0;
        *reinterpret_cast<float2*>(o1 + nf * 8) = v1;
    }
}

extern "C" void kernel_launch(void* const* d_in, const int* in_sizes, int n_in,
                              void* d_out, int out_size) {
    const float* x        = (const float*)d_in[0];
    const int*   clusters = (const int*)d_in[1];   // int32 or int64; decoded on device
    const float* W        = (const float*)d_in[2];
    const float* bias     = (const float*)d_in[3];
    float*       out      = (float*)d_out;

    cudaFuncSetAttribute(mm_kernel, cudaFuncAttributeMaxDynamicSharedMemorySize, SMEM_TOTAL);

    prep_kernel<<<1, 256>>>(clusters);
    convw_kernel<<<(G_CL * P_OUT * K_PAD + 255) / 256, 256>>>(W);
    mm_kernel<<<MAX_TASKS, THREADS, SMEM_TOTAL>>>(x, bias, out);
}

// round 6
// speedup vs baseline: 4.0447x; 1.3726x over previous
#include <cuda_runtime.h>
#include <cuda_fp16.h>
#include <cstdint>

#define B_BATCH 64
#define C_CH    862
#define S_LEN   720
#define P_OUT   336
#define G_CL    8
#define KC      32
#define NCHK    23          // ceil(720/32); chunk 22 is half zero-padded
#define K_PAD   736
#define MAX_TASKS 435
#define THREADS 512

// ---------------- device scratch ----------------
__device__ int g_task_c0[MAX_TASKS];
__device__ int g_task_c1[MAX_TASKS];
__device__ int g_task_g[MAX_TASKS];
__device__ int g_cl[C_CH];
__device__ int g_order[C_CH];
__device__ int g_cnt[G_CL];
__device__ int g_off[G_CL];
__device__ int g_pairoff[G_CL + 1];
__device__ int g_cursor[G_CL];

// Pre-converted W (fp16), K padded to 736 with zeros. ~4 MB static.
__device__ __half g_Wh[G_CL * P_OUT * K_PAD];

// ---------------- helpers ----------------
__device__ __forceinline__ uint32_t smem_u32(const void* p) {
    uint32_t a;
    asm("{ .reg .u64 t; cvta.to.shared.u64 t, %1; cvt.u32.u64 %0, t; }" : "=r"(a) : "l"(p));
    return a;
}
__device__ __forceinline__ uint32_t swz64(uint32_t o) { return o ^ ((o >> 3) & 0x30); }

__device__ __forceinline__ void ldsm4(uint32_t* r, uint32_t addr) {
    asm volatile("ldmatrix.sync.aligned.m8n8.x4.shared.b16 {%0,%1,%2,%3}, [%4];"
                 : "=r"(r[0]), "=r"(r[1]), "=r"(r[2]), "=r"(r[3]) : "r"(addr));
}
__device__ __forceinline__ void ldsm2(uint32_t* r, uint32_t addr) {
    asm volatile("ldmatrix.sync.aligned.m8n8.x2.shared.b16 {%0,%1}, [%2];"
                 : "=r"(r[0]), "=r"(r[1]) : "r"(addr));
}
__device__ __forceinline__ void mma16816(float* c, const uint32_t* a, uint32_t b0, uint32_t b1) {
    asm volatile(
        "mma.sync.aligned.m16n8k16.row.col.f32.f16.f16.f32 "
        "{%0,%1,%2,%3}, {%4,%5,%6,%7}, {%8,%9}, {%0,%1,%2,%3};"
        : "+f"(c[0]), "+f"(c[1]), "+f"(c[2]), "+f"(c[3])
        : "r"(a[0]), "r"(a[1]), "r"(a[2]), "r"(a[3]), "r"(b0), "r"(b1));
}
__device__ __forceinline__ void cpasync16(uint32_t dst, const void* src) {
    asm volatile("cp.async.cg.shared.global [%0], [%1], 16;" :: "r"(dst), "l"(src) : "memory");
}
__device__ __forceinline__ void cp_commit() { asm volatile("cp.async.commit_group;" ::: "memory"); }
__device__ __forceinline__ void cp_wait0()  { asm volatile("cp.async.wait_group 0;" ::: "memory"); }

__device__ __forceinline__ uint32_t pack2h(__half a, __half b) {
    uint16_t ua = *reinterpret_cast<uint16_t*>(&a);
    uint16_t ub = *reinterpret_cast<uint16_t*>(&b);
    return (uint32_t)ua | ((uint32_t)ub << 16);
}
// Store 4 floats as fp16 hi into hi tile and residual lo into lo tile (8B each, swizzled).
__device__ __forceinline__ void store_hi_lo(char* hi_t, char* lo_t, uint32_t boff, float4 v) {
    __half h0 = __float2half(v.x), h1 = __float2half(v.y),
           h2 = __float2half(v.z), h3 = __float2half(v.w);
    float l0 = v.x - __half2float(h0), l1 = v.y - __half2float(h1),
          l2 = v.z - __half2float(h2), l3 = v.w - __half2float(h3);
    uint2 hp, lp;
    hp.x = pack2h(h0, h1); hp.y = pack2h(h2, h3);
    lp.x = pack2h(__float2half(l0), __float2half(l1));
    lp.y = pack2h(__float2half(l2), __float2half(l3));
    uint32_t s = swz64(boff);
    *reinterpret_cast<uint2*>(hi_t + s) = hp;
    *reinterpret_cast<uint2*>(lo_t + s) = lp;
}

// ---------------- SMEM layout ----------------
#define SM_BIAS   0          // 336 * 4 = 1344
#define SM_BUF0   2048
#define OFF_AHI   0          // 128 rows * 64B = 8192
#define OFF_ALO   8192
#define OFF_BHI   16384      // 336 rows * 64B = 21504
#define BUF_BYTES 37888
#define SMEM_TOTAL (SM_BUF0 + 2 * BUF_BYTES)  // 77824

// ---------------- fused: W fp32 -> fp16 (blocks 0..N-2) + prep (last block) ----------------
#define CONV_TOTAL (G_CL * P_OUT * K_PAD)
#define CONV_BLOCKS ((CONV_TOTAL + 255) / 256)

__global__ void prep_conv_kernel(const float* __restrict__ W, const int* __restrict__ cl) {
    if (blockIdx.x < CONV_BLOCKS) {
        int idx = blockIdx.x * 256 + threadIdx.x;
        if (idx < CONV_TOTAL) {
            int k = idx % K_PAD;
            int row = idx / K_PAD;
            float v = (k < S_LEN) ? W[(size_t)row * S_LEN + k] : 0.0f;
            g_Wh[idx] = __float2half(v);
        }
        return;
    }
    // ---- prep block ----
    __shared__ int is64_s;
    const int tid = threadIdx.x;
    if (tid == 0) {
        int odd_zero = 1;
        #pragma unroll
        for (int i = 1; i < 32; i += 2) odd_zero &= (cl[i] == 0);
        is64_s = odd_zero;
    }
    if (tid < G_CL) { g_cnt[tid] = 0; g_cursor[tid] = 0; }
    __syncthreads();
    const int is64 = is64_s;
    for (int c = tid; c < C_CH; c += blockDim.x) {
        int g = is64 ? cl[2 * c] : cl[c];
        g_cl[c] = g;
        atomicAdd(&g_cnt[g], 1);
    }
    __syncthreads();
    if (tid == 0) {
        int o = 0, po = 0;
        for (int g = 0; g < G_CL; g++) {
            g_off[g] = o; g_pairoff[g] = po;
            o += g_cnt[g]; po += (g_cnt[g] + 1) >> 1;
        }
        g_pairoff[G_CL] = po;
    }
    __syncthreads();
    for (int c = tid; c < C_CH; c += blockDim.x) {
        int g = g_cl[c];
        int pos = g_off[g] + atomicAdd(&g_cursor[g], 1);
        g_order[pos] = c;
    }
    __syncthreads();
    const int total = g_pairoff[G_CL];
    for (int t = tid; t < MAX_TASKS; t += blockDim.x) {
        int c0 = -1, c1 = -1, gg = 0;
        if (t < total) {
            int g = 0;
            while (t >= g_pairoff[g + 1]) g++;
            int p = t - g_pairoff[g];
            c0 = g_order[g_off[g] + 2 * p];
            c1 = (2 * p + 1 < g_cnt[g]) ? g_order[g_off[g] + 2 * p + 1] : -1;
            gg = g;
        }
        g_task_c0[t] = c0; g_task_c1[t] = c1; g_task_g[t] = gg;
    }
}

// ---------------- main GEMM kernel (mma.sync fp16, 2-term split) ----------------
__global__ __launch_bounds__(THREADS, 1)
void mm_kernel(const float* __restrict__ x,
               const float* __restrict__ bias,
               float* __restrict__ out) {
    const int task = blockIdx.x;
    const int c0 = g_task_c0[task];
    if (c0 < 0) return;
    const int c1 = g_task_c1[task];
    const int g  = g_task_g[task];

    extern __shared__ char smem[];
    const uint32_t sbase = smem_u32(smem);
    const int tid  = threadIdx.x;
    const int lane = tid & 31;
    const int wid  = tid >> 5;
    const int warp_m = wid & 7;      // 8 m-slices of 16 rows
    const int warp_n = wid >> 3;     // 2 n-slices of 168

    for (int j = tid; j < P_OUT; j += THREADS)
        *reinterpret_cast<float*>(smem + SM_BIAS + 4 * j) = bias[g * P_OUT + j];

    // Per-lane swizzled base offsets (within region, chunk-invariant).
    const uint32_t a_swz  = swz64((uint32_t)((warp_m * 16 + (lane & 15)) * 64 + ((lane >> 4) & 1) * 16));
    const uint32_t b_swz  = swz64((uint32_t)((((lane >> 4) & 1) * 8 + (lane & 7)) * 64 + ((lane >> 3) & 1) * 16));
    const uint32_t b2_swz = swz64((uint32_t)((lane & 7) * 64 + ((lane >> 3) & 1) * 16));
    const uint32_t bn_off = (uint32_t)(warp_n * 168 * 64);  // n-slice byte offset

    const __half* wh = g_Wh + (size_t)g * P_OUT * K_PAD;

    float acc[21][4];
    #pragma unroll
    for (int i = 0; i < 21; i++)
        #pragma unroll
        for (int j = 0; j < 4; j++) acc[i][j] = 0.0f;

    // ---- chunk loaders ----
    auto loadA = [&](int chunk, int buf) {
        char* bptr = smem + SM_BUF0 + buf * BUF_BYTES;
        const int k0 = chunk * KC;
        #pragma unroll
        for (int it = 0; it < 2; it++) {
            int idx = tid + it * THREADS;       // 0..1023
            int row = idx >> 3;                 // 0..127
            int col4 = (idx & 7) << 2;          // 0..28
            int ch = (row < 64) ? c0 : c1;
            float4 v = make_float4(0.f, 0.f, 0.f, 0.f);
            if (ch >= 0 && (k0 + col4 + 3) < S_LEN)
                v = *reinterpret_cast<const float4*>(
                        x + ((size_t)(row & 63) * C_CH + ch) * S_LEN + k0 + col4);
            store_hi_lo(bptr + OFF_AHI, bptr + OFF_ALO, (uint32_t)(row * 64 + col4 * 2), v);
        }
    };
    auto issueB = [&](int chunk, int buf) {
        const uint32_t bufb = sbase + SM_BUF0 + buf * BUF_BYTES;
        const int k0 = chunk * KC;
        for (int e = tid; e < 1344; e += THREADS) {   // 336 rows * 4 x 16B units
            int row = e >> 2;
            int unit = e & 3;
            uint32_t dst = bufb + OFF_BHI + swz64((uint32_t)(row * 64 + unit * 16));
            const __half* src = wh + (size_t)row * K_PAD + k0 + unit * 8;
            cpasync16(dst, src);
        }
        cp_commit();
    };

    // ---- pipeline ----
    loadA(0, 0);
    issueB(0, 0);

    for (int i = 0; i < NCHK; i++) {
        const int buf = i & 1;
        cp_wait0();
        __syncthreads();
        if (i + 1 < NCHK) { loadA(i + 1, buf ^ 1); issueB(i + 1, buf ^ 1); }

        const uint32_t bufb = sbase + SM_BUF0 + buf * BUF_BYTES;
        #pragma unroll
        for (int k16 = 0; k16 < 2; k16++) {
            const uint32_t ko = (uint32_t)(k16 << 5);
            uint32_t ah[4], al[4];
            ldsm4(ah, bufb + OFF_AHI + (a_swz ^ ko));
            ldsm4(al, bufb + OFF_ALO + (a_swz ^ ko));
            const uint32_t bhib = bufb + OFF_BHI + bn_off;
            #pragma unroll
            for (int p = 0; p < 10; p++) {
                uint32_t bh[4];
                ldsm4(bh, bhib + p * 1024 + (b_swz ^ ko));
                mma16816(acc[2 * p],     ah, bh[0], bh[1]);
                mma16816(acc[2 * p],     al, bh[0], bh[1]);
                mma16816(acc[2 * p + 1], ah, bh[2], bh[3]);
                mma16816(acc[2 * p + 1], al, bh[2], bh[3]);
            }
            uint32_t bh2[2];
            ldsm2(bh2, bhib + 10240 + (b2_swz ^ ko));
            mma16816(acc[20], ah, bh2[0], bh2[1]);
            mma16816(acc[20], al, bh2[0], bh2[1]);
        }
    }

    // ---- epilogue ----
    const int chan = (warp_m < 4) ? c0 : c1;
    if (chan < 0) return;
    const int r0 = warp_m * 16 + (lane >> 2);        // 0..127
    const int ncol = warp_n * 168 + (lane & 3) * 2;
    float* o0 = out + ((size_t)(r0 & 63) * C_CH + chan) * P_OUT + ncol;
    float* o1 = out + ((size_t)((r0 + 8) & 63) * C_CH + chan) * P_OUT + ncol;
    const char* bsm = smem + SM_BIAS + 4 * ncol;
    #pragma unroll
    for (int nf = 0; nf < 21; nf++) {
        float2 bv = *reinterpret_cast<const float2*>(bsm + nf * 32);
        float2 v0 = make_float2(acc[nf][0] + bv.x, acc[nf][1] + bv.y);
        float2 v1 = make_float2(acc[nf][2] + bv.x, acc[nf][3] + bv.y);
        *reinterpret_cast<float2*>(o0 + nf * 8) = v0;
        *reinterpret_cast<float2*>(o1 + nf * 8) = v1;
    }
}

extern "C" void kernel_launch(void* const* d_in, const int* in_sizes, int n_in,
                              void* d_out, int out_size) {
    const float* x        = (const float*)d_in[0];
    const int*   clusters = (const int*)d_in[1];   // int32 or int64; decoded on device
    const float* W        = (const float*)d_in[2];
    const float* bias     = (const float*)d_in[3];
    float*       out      = (float*)d_out;

    cudaFuncSetAttribute(mm_kernel, cudaFuncAttributeMaxDynamicSharedMemorySize, SMEM_TOTAL);

    prep_conv_kernel<<<CONV_BLOCKS + 1, 256>>>(W, clusters);
    mm_kernel<<<MAX_TASKS, THREADS, SMEM_TOTAL>>>(x, bias, out);
}

// round 8
// speedup vs baseline: 6.5793x; 1.6266x over previous
#include <cuda_runtime.h>
#include <cuda_fp16.h>
#include <cstdint>

#define B_BATCH 64
#define C_CH    862
#define S_LEN   720
#define P_OUT   336
#define G_CL    8
#define KC      32
#define NCHK    23          // ceil(720/32); chunk 22 is half zero-padded
#define K_PAD   736
#define MAX_TASKS 435
#define THREADS 512

// ---------------- device scratch ----------------
__device__ int g_task_c0[MAX_TASKS];
__device__ int g_task_c1[MAX_TASKS];
__device__ int g_task_g[MAX_TASKS];
__device__ int g_cl[C_CH];
__device__ int g_order[C_CH];
__device__ int g_cnt[G_CL];
__device__ int g_off[G_CL];
__device__ int g_pairoff[G_CL + 1];
__device__ int g_cursor[G_CL];

// Pre-converted W (fp16), K padded to 736 with zeros. ~4 MB static.
__device__ __half g_Wh[G_CL * P_OUT * K_PAD];

// ---------------- helpers ----------------
__device__ __forceinline__ uint32_t smem_u32(const void* p) {
    uint32_t a;
    asm("{ .reg .u64 t; cvta.to.shared.u64 t, %1; cvt.u32.u64 %0, t; }" : "=r"(a) : "l"(p));
    return a;
}
__device__ __forceinline__ uint32_t swz64(uint32_t o) { return o ^ ((o >> 3) & 0x30); }

__device__ __forceinline__ void ldsm4(uint32_t* r, uint32_t addr) {
    asm volatile("ldmatrix.sync.aligned.m8n8.x4.shared.b16 {%0,%1,%2,%3}, [%4];"
                 : "=r"(r[0]), "=r"(r[1]), "=r"(r[2]), "=r"(r[3]) : "r"(addr));
}
__device__ __forceinline__ void ldsm2(uint32_t* r, uint32_t addr) {
    asm volatile("ldmatrix.sync.aligned.m8n8.x2.shared.b16 {%0,%1}, [%2];"
                 : "=r"(r[0]), "=r"(r[1]) : "r"(addr));
}
__device__ __forceinline__ void mma16816(float* c, const uint32_t* a, uint32_t b0, uint32_t b1) {
    asm volatile(
        "mma.sync.aligned.m16n8k16.row.col.f32.f16.f16.f32 "
        "{%0,%1,%2,%3}, {%4,%5,%6,%7}, {%8,%9}, {%0,%1,%2,%3};"
        : "+f"(c[0]), "+f"(c[1]), "+f"(c[2]), "+f"(c[3])
        : "r"(a[0]), "r"(a[1]), "r"(a[2]), "r"(a[3]), "r"(b0), "r"(b1));
}
__device__ __forceinline__ void cpasync16(uint32_t dst, const void* src) {
    asm volatile("cp.async.cg.shared.global [%0], [%1], 16;" :: "r"(dst), "l"(src) : "memory");
}
__device__ __forceinline__ void cp_commit() { asm volatile("cp.async.commit_group;" ::: "memory"); }
__device__ __forceinline__ void cp_wait0()  { asm volatile("cp.async.wait_group 0;" ::: "memory"); }

__device__ __forceinline__ uint32_t pack2h(__half a, __half b) {
    uint16_t ua = *reinterpret_cast<uint16_t*>(&a);
    uint16_t ub = *reinterpret_cast<uint16_t*>(&b);
    return (uint32_t)ua | ((uint32_t)ub << 16);
}

// ---------------- SMEM layout ----------------
#define SM_BIAS   0          // 336 * 4 = 1344
#define SM_BUF0   2048
#define OFF_A     0          // 128 rows * 64B = 8192
#define OFF_B     8192       // 336 rows * 64B = 21504
#define BUF_BYTES 29696
#define SMEM_TOTAL (SM_BUF0 + 2 * BUF_BYTES)  // 61440

// ---------------- fused: W fp32 -> fp16 (blocks 0..N-2) + prep (last block) ----------------
#define CONV_TOTAL (G_CL * P_OUT * K_PAD)
#define CONV_BLOCKS ((CONV_TOTAL + 255) / 256)

__global__ void prep_conv_kernel(const float* __restrict__ W, const int* __restrict__ cl) {
    if (blockIdx.x < CONV_BLOCKS) {
        int idx = blockIdx.x * 256 + threadIdx.x;
        if (idx < CONV_TOTAL) {
            int k = idx % K_PAD;
            int row = idx / K_PAD;
            float v = (k < S_LEN) ? W[(size_t)row * S_LEN + k] : 0.0f;
            g_Wh[idx] = __float2half(v);
        }
        return;
    }
    // ---- prep block ----
    __shared__ int is64_s;
    const int tid = threadIdx.x;
    if (tid == 0) {
        int odd_zero = 1;
        #pragma unroll
        for (int i = 1; i < 32; i += 2) odd_zero &= (cl[i] == 0);
        is64_s = odd_zero;
    }
    if (tid < G_CL) { g_cnt[tid] = 0; g_cursor[tid] = 0; }
    __syncthreads();
    const int is64 = is64_s;
    for (int c = tid; c < C_CH; c += blockDim.x) {
        int g = is64 ? cl[2 * c] : cl[c];
        g_cl[c] = g;
        atomicAdd(&g_cnt[g], 1);
    }
    __syncthreads();
    if (tid == 0) {
        int o = 0, po = 0;
        for (int g = 0; g < G_CL; g++) {
            g_off[g] = o; g_pairoff[g] = po;
            o += g_cnt[g]; po += (g_cnt[g] + 1) >> 1;
        }
        g_pairoff[G_CL] = po;
    }
    __syncthreads();
    for (int c = tid; c < C_CH; c += blockDim.x) {
        int g = g_cl[c];
        int pos = g_off[g] + atomicAdd(&g_cursor[g], 1);
        g_order[pos] = c;
    }
    __syncthreads();
    const int total = g_pairoff[G_CL];
    for (int t = tid; t < MAX_TASKS; t += blockDim.x) {
        int c0 = -1, c1 = -1, gg = 0;
        if (t < total) {
            int g = 0;
            while (t >= g_pairoff[g + 1]) g++;
            int p = t - g_pairoff[g];
            c0 = g_order[g_off[g] + 2 * p];
            c1 = (2 * p + 1 < g_cnt[g]) ? g_order[g_off[g] + 2 * p + 1] : -1;
            gg = g;
        }
        g_task_c0[t] = c0; g_task_c1[t] = c1; g_task_g[t] = gg;
    }
}

// ---------------- main GEMM kernel (mma.sync fp16, single pass) ----------------
__global__ __launch_bounds__(THREADS, 1)
void mm_kernel(const float* __restrict__ x,
               const float* __restrict__ bias,
               float* __restrict__ out) {
    const int task = blockIdx.x;
    const int c0 = g_task_c0[task];
    if (c0 < 0) return;
    const int c1 = g_task_c1[task];
    const int g  = g_task_g[task];

    extern __shared__ char smem[];
    const uint32_t sbase = smem_u32(smem);
    const int tid  = threadIdx.x;
    const int lane = tid & 31;
    const int wid  = tid >> 5;
    const int warp_m = wid & 7;      // 8 m-slices of 16 rows
    const int warp_n = wid >> 3;     // 2 n-slices of 168

    for (int j = tid; j < P_OUT; j += THREADS)
        *reinterpret_cast<float*>(smem + SM_BIAS + 4 * j) = bias[g * P_OUT + j];

    // Per-lane swizzled base offsets (chunk-invariant).
    const uint32_t a_swz  = swz64((uint32_t)((warp_m * 16 + (lane & 15)) * 64 + ((lane >> 4) & 1) * 16));
    const uint32_t b_swz  = swz64((uint32_t)((((lane >> 4) & 1) * 8 + (lane & 7)) * 64 + ((lane >> 3) & 1) * 16));
    const uint32_t b2_swz = swz64((uint32_t)((lane & 7) * 64 + ((lane >> 3) & 1) * 16));
    const uint32_t bn_off = (uint32_t)(warp_n * 168 * 64);

    const __half* wh = g_Wh + (size_t)g * P_OUT * K_PAD;

    float acc[21][4];
    #pragma unroll
    for (int i = 0; i < 21; i++)
        #pragma unroll
        for (int j = 0; j < 4; j++) acc[i][j] = 0.0f;

    // Per-thread A-load geometry: two float4 rows per thread (idx, idx+512).
    // idx -> row = idx>>3 (0..127), col4 = (idx&7)<<2.
    float4 aregs[2];
    const int a_row0  = tid >> 3;            // 0..63
    const int a_col4  = (tid & 7) << 2;
    const int a_row1  = a_row0 + 64;

    auto ldgA = [&](int chunk) {
        const int k0 = chunk * KC;
        const bool kok = (k0 + a_col4 + 3) < S_LEN;
        aregs[0] = make_float4(0.f, 0.f, 0.f, 0.f);
        aregs[1] = make_float4(0.f, 0.f, 0.f, 0.f);
        if (kok) {
            aregs[0] = *reinterpret_cast<const float4*>(
                x + ((size_t)a_row0 * C_CH + c0) * S_LEN + k0 + a_col4);
            if (c1 >= 0)
                aregs[1] = *reinterpret_cast<const float4*>(
                    x + ((size_t)a_row0 * C_CH + c1) * S_LEN + k0 + a_col4);
        }
    };
    auto stA = [&](int buf) {
        char* bptr = smem + SM_BUF0 + buf * BUF_BYTES + OFF_A;
        #pragma unroll
        for (int it = 0; it < 2; it++) {
            const int row = it == 0 ? a_row0 : a_row1;
            float4 v = aregs[it];
            uint2 hp;
            hp.x = pack2h(__float2half(v.x), __float2half(v.y));
            hp.y = pack2h(__float2half(v.z), __float2half(v.w));
            *reinterpret_cast<uint2*>(bptr + swz64((uint32_t)(row * 64 + a_col4 * 2))) = hp;
        }
    };
    auto issueB = [&](int chunk, int buf) {
        const uint32_t bufb = sbase + SM_BUF0 + buf * BUF_BYTES + OFF_B;
        const int k0 = chunk * KC;
        #pragma unroll
        for (int it = 0; it < 3; it++) {
            int e = tid + it * THREADS;          // 0..1343
            if (e < 1344) {
                int row = e >> 2;
                int unit = e & 3;
                uint32_t dst = bufb + swz64((uint32_t)(row * 64 + unit * 16));
                cpasync16(dst, wh + (size_t)row * K_PAD + k0 + unit * 8);
            }
        }
        cp_commit();
    };

    // ---- pipeline prologue ----
    ldgA(0);
    stA(0);
    issueB(0, 0);

    for (int i = 0; i < NCHK; i++) {
        const int buf = i & 1;
        const bool more = (i + 1 < NCHK);
        if (more) ldgA(i + 1);                 // LDG in flight under this chunk's MMAs
        cp_wait0();                            // B(i) landed
        __syncthreads();                       // A(i) visible; buf^1 free for writes
        if (more) issueB(i + 1, buf ^ 1);

        const uint32_t bufb = sbase + SM_BUF0 + buf * BUF_BYTES;
        #pragma unroll
        for (int k16 = 0; k16 < 2; k16++) {
            const uint32_t ko = (uint32_t)(k16 << 5);
            uint32_t ah[4];
            ldsm4(ah, bufb + OFF_A + (a_swz ^ ko));
            const uint32_t bb = bufb + OFF_B + bn_off;
            #pragma unroll
            for (int p = 0; p < 10; p += 2) {
                uint32_t bh0[4], bh1[4];
                ldsm4(bh0, bb + p * 1024 + (b_swz ^ ko));
                ldsm4(bh1, bb + (p + 1) * 1024 + (b_swz ^ ko));
                mma16816(acc[2 * p],     ah, bh0[0], bh0[1]);
                mma16816(acc[2 * p + 1], ah, bh0[2], bh0[3]);
                mma16816(acc[2 * p + 2], ah, bh1[0], bh1[1]);
                mma16816(acc[2 * p + 3], ah, bh1[2], bh1[3]);
            }
            uint32_t bh2[2];
            ldsm2(bh2, bb + 10240 + (b2_swz ^ ko));
            mma16816(acc[20], ah, bh2[0], bh2[1]);
        }
        if (more) stA(buf ^ 1);                // convert+store after MMAs (LDG hidden)
    }

    // ---- epilogue ----
    const int chan = (warp_m < 4) ? c0 : c1;
    if (chan < 0) return;
    const int r0 = warp_m * 16 + (lane >> 2);        // 0..127
    const int ncol = warp_n * 168 + (lane & 3) * 2;
    float* o0 = out + ((size_t)(r0 & 63) * C_CH + chan) * P_OUT + ncol;
    float* o1 = out + ((size_t)((r0 + 8) & 63) * C_CH + chan) * P_OUT + ncol;
    const char* bsm = smem + SM_BIAS + 4 * ncol;
    #pragma unroll
    for (int nf = 0; nf < 21; nf++) {
        float2 bv = *reinterpret_cast<const float2*>(bsm + nf * 32);
        float2 v0 = make_float2(acc[nf][0] + bv.x, acc[nf][1] + bv.y);
        float2 v1 = make_float2(acc[nf][2] + bv.x, acc[nf][3] + bv.y);
        *reinterpret_cast<float2*>(o0 + nf * 8) = v0;
        *reinterpret_cast<float2*>(o1 + nf * 8) = v1;
    }
}

extern "C" void kernel_launch(void* const* d_in, const int* in_sizes, int n_in,
                              void* d_out, int out_size) {
    const float* x        = (const float*)d_in[0];
    const int*   clusters = (const int*)d_in[1];   // int32 or int64; decoded on device
    const float* W        = (const float*)d_in[2];
    const float* bias     = (const float*)d_in[3];
    float*       out      = (float*)d_out;

    cudaFuncSetAttribute(mm_kernel, cudaFuncAttributeMaxDynamicSharedMemorySize, SMEM_TOTAL);

    prep_conv_kernel<<<CONV_BLOCKS + 1, 256>>>(W, clusters);
    mm_kernel<<<MAX_TASKS, THREADS, SMEM_TOTAL>>>(x, bias, out);
}